// round 17
// baseline (speedup 1.0000x reference)
#include <cuda_runtime.h>
#include <cstdint>

// Problem constants
#define BB   64
#define DD   920
#define NSMP 920
#define KK   32
#define TOT  (BB * NSMP * DD)   // 54,169,600
#define HALF (TOT / 2)          // 27,084,800
#define NCTA ((NSMP / 4) * (BB / 2))   // 7360 CTAs in the fused grid
#define RCAP 64                  // per-region candidate capacity
#define DPAD 928                 // padded threshold-table width

// Fixed-point accumulator for s[b,k]: sum of round(wa*2^22), <= 920*2^22 < 2^32.
// Zero-initialized at module load; the last-CTA epilogue restores it to zero
// after each consumption, so every launch / graph replay starts from 0.
__device__ unsigned g_s[BB * KK];     // 8 KB
__device__ unsigned g_ticket;         // last-CTA election; re-armed to 0
__device__ float    g_t0[BB];         // per-batch candidate threshold (prep)
__device__ unsigned g_B[BB * DD];     // bits-domain filter thresholds (prep)

#define QSCALE 4194304.0f             // 2^22

// Pairwise named barrier: only the two warps sharing a row-pair sync.
#define PAIR_BAR(id) asm volatile("bar.sync %0, 64;" :: "r"(id) : "memory")

// ---------------------------------------------------------------------------
// threefry2x32 (JAX-exact), both outputs returned
// ---------------------------------------------------------------------------
__device__ __forceinline__ unsigned rotl32(unsigned x, int r) {
    return __funnelshift_l(x, x, r);
}

__device__ __forceinline__ uint2 threefry(unsigned c0, unsigned c1) {
    const unsigned ks0 = 0u, ks1 = 1u, ks2 = 0x1BD11BDAu ^ 0u ^ 1u;
    unsigned x0 = c0 + ks0;
    unsigned x1 = c1 + ks1;
#define RND(r) { x0 += x1; x1 = rotl32(x1, r); x1 ^= x0; }
    RND(13) RND(15) RND(26) RND(6)   x0 += ks1; x1 += ks2 + 1u;
    RND(17) RND(29) RND(16) RND(24)  x0 += ks2; x1 += ks0 + 2u;
    RND(13) RND(15) RND(26) RND(6)   x0 += ks0; x1 += ks1 + 3u;
    RND(17) RND(29) RND(16) RND(24)  x0 += ks1; x1 += ks2 + 4u;
    RND(13) RND(15) RND(26) RND(6)   x0 += ks2; x1 += ks0 + 5u;
#undef RND
    return make_uint2(x0, x1);
}

// bits -> u in [-1, 1): identical expression to all prior passing rounds.
__device__ __forceinline__ float bits_to_u(unsigned b) {
    const float LO = -0.99999994f;  // nextafterf(-1,0)
    float f = __uint_as_float((b >> 9) | 0x3f800000u) - 1.0f;
    return fmaxf(LO, f * 2.0f + LO);
}

// Rare (w >= 5, ~0.34% per value) tail: identical to prior rounds.
__device__ __noinline__ float erfinv_tail5(float u, float w) {
    w = sqrtf(w) - 3.0f;
    float p = -0.000200214257f;
    p = fmaf(p, w, 0.000100950558f);
    p = fmaf(p, w, 0.00134934322f);
    p = fmaf(p, w, -0.00367342844f);
    p = fmaf(p, w, 0.00573950773f);
    p = fmaf(p, w, -0.0076224613f);
    p = fmaf(p, w, 0.00943887047f);
    p = fmaf(p, w, 1.00167406f);
    p = fmaf(p, w, 2.83297682f);
    return 1.41421356f * (p * u);
}

// u -> sqrt(2)*erfinv(u), bit-identical to prior rounds' per-value math.
__device__ __forceinline__ float nrm(float u) {
    float x2 = u * u;
    float om = fmaf(x2, -1.0f, 1.0f);
    float w = -__logf(om);
    if (__builtin_expect(w < 5.0f, 1)) {
        w -= 2.5f;
        float p = 2.81022636e-08f;
        p = fmaf(p, w, 3.43273939e-07f);
        p = fmaf(p, w, -3.5233877e-06f);
        p = fmaf(p, w, -4.39150654e-06f);
        p = fmaf(p, w, 0.00021858087f);
        p = fmaf(p, w, -0.00125372503f);
        p = fmaf(p, w, -0.00417768164f);
        p = fmaf(p, w, 0.246640727f);
        p = fmaf(p, w, 1.50140941f);
        return (p * u) * 1.41421356f;
    }
    return erfinv_tail5(u, w);
}

// Exact-inverse bits-domain filter threshold (prep-time only).
__device__ __forceinline__ unsigned mkB_exact(float wav, float C) {
    float cw = C - wav;
    if (cw <= 1e-4f) return 0u;                      // always pass
    float x = fmaf(10.0f, cw, -1e-3f) * 0.70710678f;
    float ub = fminf(erff(x), 0.999998f);            // cap: keep (M+1)<<9 < 2^32
    int M = (int)floorf((ub + 1.0f) * 4194304.0f) - 2;
    if (M < 0) return 0u;                            // always pass
    return ((unsigned)(M + 1)) << 9;
}

// ---------------------------------------------------------------------------
// Prep: one CTA (256 thr) per b.  Warp 0 bisects t0 (count(wa > t0) ~ 48-49),
// then ALL 256 threads fill the bits-threshold row (4 erff each, not 29).
// ---------------------------------------------------------------------------
__global__ void __launch_bounds__(256) prep_kernel(const float* __restrict__ wa) {
    __shared__ float s_C;
    int gw = blockIdx.x;
    const float* row = wa + gw * DD;
    if (threadIdx.x < 32) {
        int lane = threadIdx.x;
        float v[29];
#pragma unroll
        for (int s = 0; s < 29; s++) {
            int d = s * 32 + lane;
            v[s] = (d < DD) ? row[d] : -1e30f;
        }
        float tl = 0.80f, th = 1.05f;
        for (int it = 0; it < 22; it++) {
            float t = 0.5f * (tl + th);
            int lc = 0;
#pragma unroll
            for (int s = 0; s < 29; s++) lc += (v[s] > t) ? 1 : 0;
            int c = __reduce_add_sync(0xffffffffu, lc);
            if (c > 48) tl = t; else th = t;
        }
        if (lane == 0) {
            g_t0[gw] = tl;          // count(wa > tl) >= 49
            s_C = tl - 1e-5f;
        }
    }
    __syncthreads();
    float C = s_C;
    for (int d = threadIdx.x; d < DD; d += 256)
        g_B[gw * DD + d] = mkB_exact(row[d], C);
}

// ---------------------------------------------------------------------------
// Fallback: full bit-identical row pipeline.  Taken when c0 < 32 or a
// candidate region overflows (rare).  Scratch = the row's candidate slots.
// ---------------------------------------------------------------------------
__device__ __noinline__ void fallback_row(int b_eff, unsigned rowbase, int lane,
                                          bool useHi, const float* myrow,
                                          float* s_val, unsigned short* s_idx) {
    float v[29];
#pragma unroll
    for (int s = 0; s < 29; s++) {
        int d = s * 32 + lane;
        if (d < DD) {
            unsigned i = rowbase + (unsigned)d;
            uint2 r = threefry(i, i + (unsigned)HALF);
            float u = bits_to_u(useHi ? r.y : r.x);
            v[s] = myrow[d] + 0.1f * nrm(u);
        } else v[s] = -3.0e38f;
    }

    float t = 1.0f;
    int c = 0;
    {
        float tl = 0.85f, th = 1.15f;
        for (int it = 0; it < 8; it++) {
            int lc = 0;
#pragma unroll
            for (int s = 0; s < 29; s++) lc += (v[s] > t) ? 1 : 0;
            c = __reduce_add_sync(0xffffffffu, lc);
            if (c >= 32 && c <= 64) break;
            if (c < 32) th = t; else tl = t;
            t = 0.5f * (tl + th);
        }
    }
    if (c < 32 || c > 64) {
        float tl = -8.0f, th = 8.0f;
        t = 0.0f;
        for (int it = 0; it < 60; it++) {
            int lc = 0;
#pragma unroll
            for (int s = 0; s < 29; s++) lc += (v[s] > t) ? 1 : 0;
            c = __reduce_add_sync(0xffffffffu, lc);
            if (c >= 32 && c <= 64) break;
            if (c < 32) th = t; else tl = t;
            t = 0.5f * (tl + th);
        }
    }

    int base = 0;
    unsigned below = (1u << lane) - 1u;
#pragma unroll
    for (int s = 0; s < 29; s++) {
        bool p = v[s] > t;
        unsigned bal = __ballot_sync(0xffffffffu, p);
        if (p) {
            int pos = base + __popc(bal & below);
            if (pos < 64) {
                s_val[pos] = v[s];
                s_idx[pos] = (unsigned short)(s * 32 + lane);
            }
        }
        base += __popc(bal);
    }
    __syncwarp();

    float s0 = (lane < c)      ? s_val[lane]      : -3.0e38f;
    float s1 = (lane + 32 < c) ? s_val[lane + 32] : -3.0e38f;

    if (c != 32) {
        float til = t, tih = 1.6f;
        for (int it = 0; it < 32; it++) {
            float tm = 0.5f * (til + tih);
            unsigned b0 = __ballot_sync(0xffffffffu, s0 > tm);
            unsigned b1 = __ballot_sync(0xffffffffu, s1 > tm);
            int cc = __popc(b0) + __popc(b1);
            if (cc >= 32) til = tm; else tih = tm;
            if (cc == 32) break;
        }
        t = til;
    }

    bool k0 = s0 > t, k1 = s1 > t;
    unsigned keep0 = __ballot_sync(0xffffffffu, k0);
    unsigned keep1 = __ballot_sync(0xffffffffu, k1);
    if (k0) {
        int r = __popc(keep0 & below);
        if (r < KK) {
            int d = (int)s_idx[lane];
            atomicAdd(&g_s[b_eff * KK + r], __float2uint_rn(myrow[d] * QSCALE));
        }
    }
    if (k1) {
        int r = __popc(keep0) + __popc(keep1 & below);
        if (r < KK) {
            int d = (int)s_idx[lane + 32];
            atomicAdd(&g_s[b_eff * KK + r], __float2uint_rn(myrow[d] * QSCALE));
        }
    }
}

// ---------------------------------------------------------------------------
// Phase 2 consumer, templated on register rounds (NR=2 common, NR=4 rare).
// Returns false if the fallback must run (c0 < 32).
// ---------------------------------------------------------------------------
template <int NR>
__device__ __forceinline__ bool phase2_run(uint2* cR, int n_lo, int n_hi,
                                           float t0, const float* myrow,
                                           int b_eff, int lane, unsigned below) {
    int ntot = n_lo + n_hi;
    float sv[NR];
#pragma unroll
    for (int k = 0; k < NR; k++) sv[k] = -3.0e38f;
    int kmax = (ntot + 31) >> 5;
#pragma unroll
    for (int k = 0; k < NR; k++) {
        if (k < kmax) {
            int i = (k << 5) + lane;
            if (i < ntot) {
                int ph = (i < n_lo) ? i : (RCAP + i - n_lo);
                uint2 cd = cR[ph];
                float u = bits_to_u(cd.y);
                sv[k] = myrow[cd.x] + 0.1f * nrm(u);
            }
        }
    }
    int c0 = 0;
#pragma unroll
    for (int k = 0; k < NR; k++)
        c0 += __popc(__ballot_sync(0xffffffffu, sv[k] > t0));
    if (c0 < 32) return false;

    float t = t0;
    if (c0 != 32) {
        float til = t0, tih = 1.6f;
        for (int it = 0; it < 32; it++) {
            float tm = 0.5f * (til + tih);
            int cc = 0;
#pragma unroll
            for (int k = 0; k < NR; k++)
                cc += __popc(__ballot_sync(0xffffffffu, sv[k] > tm));
            if (cc >= 32) til = tm; else tih = tm;
            if (cc == 32) break;
        }
        t = til;
    }
    unsigned bal[NR];
#pragma unroll
    for (int k = 0; k < NR; k++)
        bal[k] = __ballot_sync(0xffffffffu, sv[k] > t);
    int pre = 0;
#pragma unroll
    for (int k = 0; k < NR; k++) {
        if (sv[k] > t) {
            int rk = pre + __popc(bal[k] & below);
            if (rk < KK) {
                int i = (k << 5) + lane;
                int ph = (i < n_lo) ? i : (RCAP + i - n_lo);
                int d = (int)cR[ph].x;
                atomicAdd(&g_s[b_eff * KK + rk],
                          __float2uint_rn(myrow[d] * QSCALE));
            }
        }
        pre += __popc(bal[k]);
    }
    return true;
}

// ---------------------------------------------------------------------------
// Fused kernel.  Phase 1: 2-way interleaved threefry (two independent 8-cyc
// dependency chains in flight), single bits-compare filter per value, ballot
// compaction ascending-d.  Pairwise named barrier (warps w, w+4 only) hands
// off to phase 2, so one pair's latency-bound selection overlaps other
// pairs' throughput-bound generation.  Last CTA folds g_s -> bboxes.
// ---------------------------------------------------------------------------
__global__ void __launch_bounds__(256, 5) ftopk_kernel(const float* __restrict__ wa,
                                                       float* __restrict__ out) {
    __shared__ float s_waA[DD];
    __shared__ float s_waB[DD];
    __shared__ uint2 s_Bp[DPAD];                     // {B_rowA, B_rowB} per d
    __shared__ uint2 s_cand[4][2][2 * RCAP];         // [pair][row][slot] (d, bits)
    __shared__ int s_cnt[4][2][2];                   // [pair][row][lo/hi]
    __shared__ bool s_last;

    int b = blockIdx.y;                 // 0..31 (pair: b and b+32)
    int warpid = threadIdx.x >> 5;
    int lane = threadIdx.x & 31;
    int wp = warpid & 3;
    bool isB = warpid >= 4;
    unsigned below = (1u << lane) - 1u;

    float t0A = g_t0[b];
    float t0B = g_t0[b + 32];
    for (int i = threadIdx.x; i < DPAD; i += 256) {
        if (i < DD) {
            s_waA[i] = wa[b * DD + i];
            s_waB[i] = wa[(b + 32) * DD + i];
            s_Bp[i] = make_uint2(g_B[b * DD + i], g_B[(b + 32) * DD + i]);
        } else {
            s_Bp[i] = make_uint2(0xFFFFFFFFu, 0xFFFFFFFFu);  // pad: never pass
        }
    }
    __syncthreads();

    int n = blockIdx.x * 4 + wp;        // gridDim.x = 230 -> n in [0,920)
    unsigned rowbase = (unsigned)((b * NSMP + n) * DD);  // < HALF (b < 32)

    // ---- phase 1: interleaved threefry + filter + compact (d,bits) ----
    {
        int baseA = 0, baseB = 0;
        uint2* candA = s_cand[wp][0] + (isB ? RCAP : 0);
        uint2* candB = s_cand[wp][1] + (isB ? RCAP : 0);

        // One filter+compact step for a generated (d, r) with both rows.
#define FSTEP(d_, r_)                                                         \
        {                                                                     \
            uint2 Bp_ = s_Bp[d_];                                             \
            bool cA_ = r_.x >= Bp_.x;                                         \
            bool cB_ = r_.y >= Bp_.y;                                         \
            unsigned balA_ = __ballot_sync(0xffffffffu, cA_);                 \
            if (cA_) {                                                        \
                int pos_ = baseA + __popc(balA_ & below);                     \
                if (pos_ < RCAP) candA[pos_] = make_uint2((unsigned)(d_), r_.x); \
            }                                                                 \
            baseA += __popc(balA_);                                           \
            unsigned balB_ = __ballot_sync(0xffffffffu, cB_);                 \
            if (cB_) {                                                        \
                int pos_ = baseB + __popc(balB_ & below);                     \
                if (pos_ < RCAP) candB[pos_] = make_uint2((unsigned)(d_), r_.y); \
            }                                                                 \
            baseB += __popc(balB_);                                           \
        }

        if (!isB) {
#pragma unroll
            for (int s = 0; s < 14; s += 2) {        // slices 0..13, pairs
                int d0 = s * 32 + lane;
                int d1 = d0 + 32;
                unsigned i0 = rowbase + (unsigned)d0;
                unsigned i1 = rowbase + (unsigned)d1;
                uint2 r0 = threefry(i0, i0 + (unsigned)HALF);
                uint2 r1 = threefry(i1, i1 + (unsigned)HALF);
                FSTEP(d0, r0)
                FSTEP(d1, r1)
            }
            {                                        // slice 14 (single)
                int d0 = 14 * 32 + lane;
                unsigned i0 = rowbase + (unsigned)d0;
                uint2 r0 = threefry(i0, i0 + (unsigned)HALF);
                FSTEP(d0, r0)
            }
        } else {
#pragma unroll
            for (int s = 15; s < 29; s += 2) {       // slices 15..28, pairs
                int d0 = s * 32 + lane;
                int d1 = d0 + 32;
                unsigned i0 = rowbase + (unsigned)d0;
                unsigned i1 = rowbase + (unsigned)d1;
                uint2 r0 = threefry(i0, i0 + (unsigned)HALF);
                uint2 r1 = threefry(i1, i1 + (unsigned)HALF);
                // only s+1 == 28 can run past DD (d1 >= 896+24*..): mask lanes
                FSTEP(d0, r0)
                if (s + 1 == 28) {
                    uint2 Bp_ = s_Bp[d1];            // padded table: safe
                    bool cA_ = (lane < 24) && (r1.x >= Bp_.x);
                    bool cB_ = (lane < 24) && (r1.y >= Bp_.y);
                    unsigned balA_ = __ballot_sync(0xffffffffu, cA_);
                    if (cA_) {
                        int pos_ = baseA + __popc(balA_ & below);
                        if (pos_ < RCAP) candA[pos_] = make_uint2((unsigned)d1, r1.x);
                    }
                    baseA += __popc(balA_);
                    unsigned balB_ = __ballot_sync(0xffffffffu, cB_);
                    if (cB_) {
                        int pos_ = baseB + __popc(balB_ & below);
                        if (pos_ < RCAP) candB[pos_] = make_uint2((unsigned)d1, r1.y);
                    }
                    baseB += __popc(balB_);
                } else {
                    FSTEP(d1, r1)
                }
            }
        }
#undef FSTEP
        if (lane == 0) {
            s_cnt[wp][0][isB ? 1 : 0] = baseA;
            s_cnt[wp][1][isB ? 1 : 0] = baseB;
        }
    }
    PAIR_BAR(1 + wp);    // only warps w and w+4 sync (64 threads)

    // ---- phase 2: consumer (one row per warp) ----
    {
        int r = isB ? 1 : 0;
        int b_eff = isB ? (b + 32) : b;
        float t0 = isB ? t0B : t0A;
        const float* myrow = isB ? s_waB : s_waA;
        uint2* cR = s_cand[wp][r];
        int n_lo = s_cnt[wp][r][0];
        int n_hi = s_cnt[wp][r][1];

        bool done = false;
        if (n_lo <= RCAP && n_hi <= RCAP) {
            int ntot = n_lo + n_hi;
            if (ntot <= 64)
                done = phase2_run<2>(cR, n_lo, n_hi, t0, myrow, b_eff, lane, below);
            else
                done = phase2_run<4>(cR, n_lo, n_hi, t0, myrow, b_eff, lane, below);
        }
        if (!done) {
            // reuse this row's candidate slots as sort scratch
            float* fv = (float*)cR;                          // 64 floats
            unsigned short* fi = (unsigned short*)(cR + 96); // 64 u16, disjoint
            fallback_row(b_eff, rowbase, lane, isB, myrow, fv, fi);
        }
    }

    // ---- last-CTA epilogue: fold g_s -> bboxes, re-arm scratch ----
    __threadfence();
    __syncthreads();
    if (threadIdx.x == 0) {
        unsigned tk = atomicAdd(&g_ticket, 1u);
        s_last = (tk == NCTA - 1u);
    }
    __syncthreads();
    if (s_last) {
        __threadfence();
        for (int idx = threadIdx.x; idx < BB * KK; idx += 256) {
            unsigned acc = atomicExch(&g_s[idx], 0u);   // read + re-zero
            float sv = __uint2float_rn(acc) * (1.0f / (QSCALE * 920.0f));
            float r  = floorf(sv / 40.0f);
            float cc = sv - 40.0f * r;                  // jnp.mod(sv, 40)
            float x0 = (cc < 1.0f ? cc : cc - 1.0f) * 32.0f;
            float y0 = (r  < 1.0f ? r  : r  - 1.0f) * 32.0f;
            float x1 = (cc < 1.0f ? cc + 2.0f : cc + 1.0f) * 32.0f;
            float y1 = (r + 2.0f) * 32.0f;
            ((float4*)out)[idx] = make_float4(x0, y0, x1, y1);
        }
        if (threadIdx.x == 0) g_ticket = 0u;
    }
}

// ---------------------------------------------------------------------------
extern "C" void kernel_launch(void* const* d_in, const int* in_sizes, int n_in,
                              void* d_out, int out_size) {
    const float* wa = (const float*)d_in[2];   // weight_attn (64,23,40) -> (64,920)
    float* out = (float*)d_out;                // (64,32,4) float32

    prep_kernel<<<BB, 256>>>(wa);
    ftopk_kernel<<<dim3(NSMP / 4, BB / 2), 256>>>(wa, out);
}